// round 13
// baseline (speedup 1.0000x reference)
#include <cuda_runtime.h>
#include <cuda_fp16.h>
#include <cuda_bf16.h>

#define B_     16
#define C_     80
#define D_     1024
#define HW_    196
#define HWP_   208
#define KP_    104            // hw-pairs (208/2)

__device__ float    g_scores[B_ * C_ * HW_];
__device__ unsigned g_img2[B_ * (D_ / 2) * HWP_];     // f16x2 d-pairs (scores)
__device__ unsigned g_word2[C_ * (D_ / 2)];           // f16x2 d-pairs (scores)
__device__ unsigned g_fwh2[D_ / 2];                   // f16x2 d-pairs (scores)
__device__ unsigned g_coef_hi[B_ * C_ * KP_];         // f16x2 hw-pairs (pool)
__device__ unsigned g_imgT_hi[B_ * D_ * KP_];         // f16x2 hw-pairs (pool)

__device__ __forceinline__ unsigned pack_h2(float a, float b) {
    unsigned r;
    asm("cvt.rn.f16x2.f32 %0, %2, %1;" : "=r"(r) : "f"(a), "f"(b));
    return r;
}
__device__ __forceinline__ unsigned tanh_h2(unsigned x) {
    unsigned y;
    asm("tanh.approx.f16x2 %0, %1;" : "=r"(y) : "r"(x));
    return y;
}
__device__ __forceinline__ unsigned mul_h2(unsigned a, unsigned b) {
    unsigned y;
    asm("mul.rn.f16x2 %0, %1, %2;" : "=r"(y) : "r"(a), "r"(b));
    return y;
}

#define MMA16816(D0,D1,D2,D3, A0,A1,A2,A3, B0,B1) \
    asm("mma.sync.aligned.m16n8k16.row.col.f32.f16.f16.f32 " \
        "{%0,%1,%2,%3}, {%4,%5,%6,%7}, {%8,%9}, {%0,%1,%2,%3};" \
        : "+f"(D0), "+f"(D1), "+f"(D2), "+f"(D3) \
        : "r"(A0), "r"(A1), "r"(A2), "r"(A3), "r"(B0), "r"(B1))

#define CPA16(saddr, gptr) \
    asm volatile("cp.async.ca.shared.global [%0], [%1], 16;" \
                 :: "r"(saddr), "l"(gptr))

// -----------------------------------------------------------------------------
// Kernel P: merged packing. Phase A: img read once -> g_img2 + g_imgT_hi.
// Phase B: word/fw -> f16x2.
// -----------------------------------------------------------------------------
#define PA_BLOCKS 416    // 16*512*13 / 256
#define PB_BLOCKS 162    // (80*512 + 512) / 256
__global__ __launch_bounds__(256) void pack_all(
    const float* __restrict__ img,
    const float* __restrict__ word,
    const float* __restrict__ fw)
{
    const int blk = blockIdx.x;
    const int tid = threadIdx.x;

    if (blk < PA_BLOCKS) {
        int idx = blk * 256 + tid;       // < 16*512*13
        int ks = idx % 13;
        int t  = idx / 13;
        int dp = t & 511;
        int b  = t >> 9;

        const float* r0 = img + ((size_t)b * D_ + 2 * dp) * HW_ + ks * 16;
        const float* r1 = r0 + HW_;
        float a[16], c[16];
        if (ks < 12) {
            #pragma unroll
            for (int j = 0; j < 4; j++) {
                float4 fa = *(const float4*)(r0 + 4 * j);
                float4 fc = *(const float4*)(r1 + 4 * j);
                a[4*j] = fa.x; a[4*j+1] = fa.y; a[4*j+2] = fa.z; a[4*j+3] = fa.w;
                c[4*j] = fc.x; c[4*j+1] = fc.y; c[4*j+2] = fc.z; c[4*j+3] = fc.w;
            }
        } else {
            float4 fa = *(const float4*)r0;
            float4 fc = *(const float4*)r1;
            a[0] = fa.x; a[1] = fa.y; a[2] = fa.z; a[3] = fa.w;
            c[0] = fc.x; c[1] = fc.y; c[2] = fc.z; c[3] = fc.w;
            #pragma unroll
            for (int j = 4; j < 16; j++) { a[j] = 0.f; c[j] = 0.f; }
        }

        unsigned* pi = &g_img2[((size_t)b * (D_ / 2) + dp) * HWP_ + ks * 16];
        #pragma unroll
        for (int j = 0; j < 4; j++) {
            uint4 o;
            o.x = pack_h2(a[4*j],   c[4*j]);
            o.y = pack_h2(a[4*j+1], c[4*j+1]);
            o.z = pack_h2(a[4*j+2], c[4*j+2]);
            o.w = pack_h2(a[4*j+3], c[4*j+3]);
            *(uint4*)(pi + 4 * j) = o;
        }
        unsigned* p0 = g_imgT_hi + ((size_t)b * D_ + 2 * dp) * KP_ + ks * 8;
        unsigned* p1 = p0 + KP_;
        uint4 oa0, oa1, oc0, oc1;
        oa0.x = pack_h2(a[0], a[1]);  oa0.y = pack_h2(a[2], a[3]);
        oa0.z = pack_h2(a[4], a[5]);  oa0.w = pack_h2(a[6], a[7]);
        oa1.x = pack_h2(a[8], a[9]);  oa1.y = pack_h2(a[10], a[11]);
        oa1.z = pack_h2(a[12], a[13]); oa1.w = pack_h2(a[14], a[15]);
        oc0.x = pack_h2(c[0], c[1]);  oc0.y = pack_h2(c[2], c[3]);
        oc0.z = pack_h2(c[4], c[5]);  oc0.w = pack_h2(c[6], c[7]);
        oc1.x = pack_h2(c[8], c[9]);  oc1.y = pack_h2(c[10], c[11]);
        oc1.z = pack_h2(c[12], c[13]); oc1.w = pack_h2(c[14], c[15]);
        *(uint4*)p0       = oa0;
        *(uint4*)(p0 + 4) = oa1;
        *(uint4*)p1       = oc0;
        *(uint4*)(p1 + 4) = oc1;
    } else {
        int idx = (blk - PA_BLOCKS) * 256 + tid;
        if (idx < C_ * (D_ / 2)) {
            int c = idx >> 9, dp = idx & 511;
            float2 w = *(const float2*)&word[(size_t)c * D_ + 2 * dp];
            g_word2[c * (D_ / 2) + dp] = pack_h2(w.x, w.y);
        } else {
            int dp = idx - C_ * (D_ / 2);   // < 512
            g_fwh2[dp] = pack_h2(fw[2 * dp], fw[2 * dp + 1]);
        }
    }
}

// -----------------------------------------------------------------------------
// Kernel A: full-D scores via HMMA, double-buffered cp.async pipeline.
// Each block reduces ALL 512 dpairs as 8 sub-chunks of 64.
// grid (13 hw16, 5 c16, 16 b) = 1040 blocks = one balanced wave.
// -----------------------------------------------------------------------------
__global__ __launch_bounds__(128) void scores_kernel()
{
    __shared__ unsigned img2_s[2][64][24];   // [buf][dpair][hw(16)+pad8]
    __shared__ unsigned word2_s[2][16][64];  // [buf][cc][dpair]
    __shared__ unsigned fwh2_s[2][64];       // [buf][dpair]

    const int tid  = threadIdx.x;
    const int warp = tid >> 5;
    const int lane = tid & 31;
    const int q    = lane & 3;
    const int g    = lane >> 2;
    const int hw0  = blockIdx.x * 16;
    const int c0   = blockIdx.y * 16;
    const int b    = blockIdx.z;

    unsigned sb_img, sb_word, sb_fw;
    asm("{ .reg .u64 t; cvta.to.shared.u64 t, %1; cvt.u32.u64 %0, t; }"
        : "=r"(sb_img) : "l"(&img2_s[0][0][0]));
    asm("{ .reg .u64 t; cvta.to.shared.u64 t, %1; cvt.u32.u64 %0, t; }"
        : "=r"(sb_word) : "l"(&word2_s[0][0][0]));
    asm("{ .reg .u64 t; cvta.to.shared.u64 t, %1; cvt.u32.u64 %0, t; }"
        : "=r"(sb_fw) : "l"(&fwh2_s[0][0]));

    const unsigned IMG_BUF  = 64 * 24 * 4;
    const unsigned WORD_BUF = 16 * 64 * 4;
    const unsigned FW_BUF   = 64 * 4;

    #define FILL(c) do {                                                        \
        const int buf_ = (c) & 1;                                               \
        const int dp0_ = (c) * 64;                                              \
        _Pragma("unroll")                                                       \
        for (int k = 0; k < 2; k++) {                                           \
            int ch  = tid + k * 128;                                            \
            int dp  = ch >> 2;                                                  \
            int off = ch & 3;                                                   \
            CPA16(sb_img + buf_ * IMG_BUF + (dp * 24 + off * 4) * 4,            \
                  g_img2 + ((size_t)b * (D_ / 2) + dp0_ + dp) * HWP_ + hw0 + off * 4); \
        }                                                                       \
        _Pragma("unroll")                                                       \
        for (int k = 0; k < 2; k++) {                                           \
            int ch  = tid + k * 128;                                            \
            int row = ch >> 4;                                                  \
            int cq  = ch & 15;                                                  \
            CPA16(sb_word + buf_ * WORD_BUF + (row * 64 + cq * 4) * 4,          \
                  g_word2 + (size_t)(c0 + row) * (D_ / 2) + dp0_ + cq * 4);     \
        }                                                                       \
        if (tid < 16)                                                           \
            CPA16(sb_fw + buf_ * FW_BUF + tid * 16, g_fwh2 + dp0_ + tid * 4);   \
        asm volatile("cp.async.commit_group;");                                 \
    } while (0)

    float dacc[4][4];
    #pragma unroll
    for (int j = 0; j < 4; j++)
        #pragma unroll
        for (int r = 0; r < 4; r++) dacc[j][r] = 0.f;

    const bool bsel = (lane < 4);

    FILL(0);

    #pragma unroll
    for (int c = 0; c < 8; c++) {
        if (c < 7) {
            FILL(c + 1);
            asm volatile("cp.async.wait_group 1;");
        } else {
            asm volatile("cp.async.wait_group 0;");
        }
        __syncthreads();

        const int buf = c & 1;
        #pragma unroll 4
        for (int kc = 0; kc < 8; kc++) {
            const int p0 = kc * 8 + q;
            const int p1 = p0 + 4;
            const unsigned iv00 = img2_s[buf][p0][g];
            const unsigned iv01 = img2_s[buf][p0][g + 8];
            const unsigned iv10 = img2_s[buf][p1][g];
            const unsigned iv11 = img2_s[buf][p1][g + 8];
            const unsigned fb0 = bsel ? fwh2_s[buf][p0] : 0u;
            const unsigned fb1 = bsel ? fwh2_s[buf][p1] : 0u;

            #pragma unroll
            for (int j = 0; j < 4; j++) {
                const int cl = warp * 4 + j;
                const unsigned wA = word2_s[buf][cl][p0];
                const unsigned wB = word2_s[buf][cl][p1];
                unsigned a0 = tanh_h2(mul_h2(iv00, wA));
                unsigned a1 = tanh_h2(mul_h2(iv01, wA));
                unsigned a2 = tanh_h2(mul_h2(iv10, wB));
                unsigned a3 = tanh_h2(mul_h2(iv11, wB));
                MMA16816(dacc[j][0], dacc[j][1], dacc[j][2], dacc[j][3],
                         a0, a1, a2, a3, fb0, fb1);
            }
        }
        __syncthreads();
    }

    if (q == 0) {
        #pragma unroll
        for (int j = 0; j < 4; j++) {
            const int c = c0 + warp * 4 + j;
            const size_t rowbase = ((size_t)b * C_ + c) * HW_;
            const int hw1 = hw0 + g;
            const int hw2 = hw0 + g + 8;
            if (hw1 < HW_) g_scores[rowbase + hw1] = dacc[j][0];
            if (hw2 < HW_) g_scores[rowbase + hw2] = dacc[j][2];
        }
    }
    #undef FILL
}

// -----------------------------------------------------------------------------
// Kernel B: softmax over 196 hw per (b,c) row -> coef hi f16x2 pairs.
// -----------------------------------------------------------------------------
__global__ __launch_bounds__(256) void softmax_kernel()
{
    const int wid  = (blockIdx.x * blockDim.x + threadIdx.x) >> 5;
    const int lane = threadIdx.x & 31;
    if (wid >= B_ * C_) return;

    const float* row = g_scores + (size_t)wid * HW_;

    float v[7];
    float m = -1e30f;
    #pragma unroll
    for (int k = 0; k < 7; k++) {
        int i = lane + 32 * k;
        v[k] = (i < HW_) ? row[i] : -1e30f;
        m = fmaxf(m, v[k]);
    }
    #pragma unroll
    for (int o = 16; o; o >>= 1) m = fmaxf(m, __shfl_xor_sync(0xffffffffu, m, o));

    float s = 0.f;
    #pragma unroll
    for (int k = 0; k < 7; k++) { v[k] = __expf(v[k] - m); s += v[k]; }
    #pragma unroll
    for (int o = 16; o; o >>= 1) s += __shfl_xor_sync(0xffffffffu, s, o);

    const float inv = 1.f / s;
    unsigned* ph = g_coef_hi + (size_t)wid * KP_;
    #pragma unroll
    for (int k = 0; k < 7; k++) {
        float mine = (lane + 32 * k < HW_) ? v[k] * inv : 0.f;
        float partner = __shfl_xor_sync(0xffffffffu, mine, 1);
        int kp = (lane >> 1) + 16 * k;
        if ((lane & 1) == 0 && kp < KP_)
            ph[kp] = pack_h2(mine, partner);
    }
}

// -----------------------------------------------------------------------------
// Kernel C (HMMA pool): coef f16 x img f16. Single pass, cp.async fill.
// grid (16 d-tiles of 64, 16 b), block 320.
// -----------------------------------------------------------------------------
#define PDT  64
#define KPS  108

__global__ __launch_bounds__(320) void pool_kernel(float* __restrict__ out)
{
    extern __shared__ unsigned psm[];
    unsigned* ch = psm;                  // coef hi [80][KPS]
    unsigned* ih = ch + C_ * KPS;        // img  hi [PDT][KPS]

    const int tid  = threadIdx.x;
    const int warp = tid >> 5;
    const int lane = tid & 31;
    const int q    = lane & 3;
    const int g    = lane >> 2;
    const int wg   = warp / 5;           // d-half: 0 or 1
    const int wi   = warp % 5;           // class tile
    const int d0   = blockIdx.x * PDT;
    const int b    = blockIdx.y;

    unsigned sbase;
    asm("{ .reg .u64 t; cvta.to.shared.u64 t, %1; cvt.u32.u64 %0, t; }"
        : "=r"(sbase) : "l"(psm));
    const unsigned ih_off = (unsigned)(C_ * KPS * 4);

    for (int i = tid; i < C_ * 26; i += 320) {
        int row = i / 26, cq = i - row * 26;
        CPA16(sbase + (row * KPS + cq * 4) * 4,
              g_coef_hi + ((size_t)b * C_ + row) * KP_ + cq * 4);
    }
    for (int i = tid; i < PDT * 26; i += 320) {
        int row = i / 26, cq = i - row * 26;
        CPA16(sbase + ih_off + (row * KPS + cq * 4) * 4,
              g_imgT_hi + ((size_t)b * D_ + d0 + row) * KP_ + cq * 4);
    }
    asm volatile("cp.async.commit_group;");

    float acc[4][4];
    #pragma unroll
    for (int t = 0; t < 4; t++)
        #pragma unroll
        for (int r = 0; r < 4; r++) acc[t][r] = 0.f;

    const int rA0 = (wi * 16 + g) * KPS;
    const int rA1 = (wi * 16 + g + 8) * KPS;
    const int dbase = wg * 32;

    asm volatile("cp.async.wait_group 0;");
    __syncthreads();

    #pragma unroll 1
    for (int ks = 0; ks < 13; ks++) {
        const int p0 = ks * 8 + q;
        const int p1 = p0 + 4;
        const unsigned ah0 = ch[rA0 + p0], ah1 = ch[rA1 + p0];
        const unsigned ah2 = ch[rA0 + p1], ah3 = ch[rA1 + p1];
        #pragma unroll
        for (int t = 0; t < 4; t++) {
            const int rB = (dbase + t * 8 + g) * KPS;
            MMA16816(acc[t][0], acc[t][1], acc[t][2], acc[t][3],
                     ah0, ah1, ah2, ah3, ih[rB + p0], ih[rB + p1]);
        }
    }

    #pragma unroll
    for (int t = 0; t < 4; t++) {
        const int dcol = d0 + dbase + t * 8 + 2 * q;
        const size_t r0 = ((size_t)b * C_ + wi * 16 + g) * D_ + dcol;
        const size_t r1 = ((size_t)b * C_ + wi * 16 + g + 8) * D_ + dcol;
        *(float2*)&out[r0] = make_float2(acc[t][0], acc[t][1]);
        *(float2*)&out[r1] = make_float2(acc[t][2], acc[t][3]);
    }
}

// -----------------------------------------------------------------------------

extern "C" void kernel_launch(void* const* d_in, const int* in_sizes, int n_in,
                              void* d_out, int out_size)
{
    const float* img  = (const float*)d_in[1];
    const float* word = (const float*)d_in[2];
    const float* fw   = (const float*)d_in[3];
    float* out = (float*)d_out;

    const int pool_smem = (C_ + PDT) * KPS * (int)sizeof(unsigned); // 62208
    cudaFuncSetAttribute(pool_kernel, cudaFuncAttributeMaxDynamicSharedMemorySize,
                         pool_smem);

    pack_all<<<PA_BLOCKS + PB_BLOCKS, 256>>>(img, word, fw);

    scores_kernel<<<dim3(13, 5, B_), 128>>>();

    softmax_kernel<<<160, 256>>>();

    pool_kernel<<<dim3(D_ / PDT, B_), 320, pool_smem>>>(out);
}